// round 14
// baseline (speedup 1.0000x reference)
#include <cuda_runtime.h>
#include <cuda_fp16.h>
#include <math.h>

#define N_NODES 50000
#define N_EDGES 800000
#define F 128
#define TM 64
#define TK 32

typedef unsigned long long u64;

// Scratch (allocation-free rule: __device__ globals)
__device__ __half2 g_hh[N_NODES * (F / 2)];  // h = feat@Wp^T+bp, fp16 pairs
__device__ float g_WpT[F * F];          // W_pool transposed: [k][c]
__device__ float g_WsT[F * F];          // W_self transposed: [k][c]
__device__ int   g_count[N_NODES];      // in-degree histogram
__device__ int   g_off[N_NODES + 1];    // CSR row offsets (by dst)
__device__ int   g_cursor[N_NODES];     // scatter cursors (init = offsets)
__device__ int2  g_edges[N_EDGES];      // dst-sorted records: {src, bits(w)}

// ---- packed f32x2 helpers (Blackwell sm_103a; ptxas never auto-fuses) ----
__device__ __forceinline__ u64 pack2(float lo, float hi) {
    u64 r; asm("mov.b64 %0, {%1, %2};" : "=l"(r) : "f"(lo), "f"(hi)); return r;
}
__device__ __forceinline__ u64 fma2(u64 a, u64 b, u64 c) {
    u64 d; asm("fma.rn.f32x2 %0, %1, %2, %3;" : "=l"(d) : "l"(a), "l"(b), "l"(c));
    return d;
}
__device__ __forceinline__ void unpack2(u64 v, float& lo, float& hi) {
    asm("mov.b64 {%0, %1}, %2;" : "=f"(lo), "=f"(hi) : "l"(v));
}

// ---------------------------------------------------------------------------
// Zero histogram + transpose weights (runs every launch; deterministic)
// ---------------------------------------------------------------------------
__global__ void zero_transpose_kernel(const float* __restrict__ Wp,
                                      const float* __restrict__ Ws) {
    int i = blockIdx.x * blockDim.x + threadIdx.x;
    if (i < N_NODES) g_count[i] = 0;
    if (i < F * F) {
        int c = i >> 7;
        int k = i & (F - 1);
        g_WpT[k * F + c] = Wp[c * F + k];
        g_WsT[k * F + c] = Ws[c * F + k];
    }
}

// ---------------------------------------------------------------------------
// In-degree histogram
// ---------------------------------------------------------------------------
__global__ void hist_kernel(const int* __restrict__ dst) {
    int e = blockIdx.x * blockDim.x + threadIdx.x;
    if (e < N_EDGES) atomicAdd(&g_count[dst[e]], 1);
}

// ---------------------------------------------------------------------------
// Single-block exclusive scan of g_count -> g_off, g_cursor
// ---------------------------------------------------------------------------
__global__ __launch_bounds__(1024) void scan_kernel() {
    const int CHUNK = (N_NODES + 1023) / 1024;   // 49
    __shared__ int warp_sums[32];
    int tid  = threadIdx.x;
    int base = tid * CHUNK;
    int hi   = min(base + CHUNK, N_NODES);

    int sum = 0;
    for (int i = base; i < hi; i++) sum += g_count[i];

    int lane = tid & 31, wid = tid >> 5;
    int v = sum;
#pragma unroll
    for (int o = 1; o < 32; o <<= 1) {
        int t = __shfl_up_sync(0xffffffff, v, o);
        if (lane >= o) v += t;
    }
    if (lane == 31) warp_sums[wid] = v;
    __syncthreads();
    if (wid == 0) {
        int wv = warp_sums[lane];
#pragma unroll
        for (int o = 1; o < 32; o <<= 1) {
            int t = __shfl_up_sync(0xffffffff, wv, o);
            if (lane >= o) wv += t;
        }
        warp_sums[lane] = wv;
    }
    __syncthreads();
    int excl = v - sum + (wid > 0 ? warp_sums[wid - 1] : 0);

    int run = excl;
    for (int i = base; i < hi; i++) {
        g_off[i]    = run;
        g_cursor[i] = run;
        run += g_count[i];
    }
    if (tid == 0) g_off[N_NODES] = N_EDGES;
}

// ---------------------------------------------------------------------------
// Scatter packed edge records into dst-sorted order
// ---------------------------------------------------------------------------
__global__ void scatter_kernel(const float* __restrict__ efeat,
                               const int* __restrict__ src,
                               const int* __restrict__ dst) {
    int e = blockIdx.x * blockDim.x + threadIdx.x;
    if (e < N_EDGES) {
        int d = dst[e];
        int pos = atomicAdd(&g_cursor[d], 1);
        g_edges[pos] = make_int2(src[e], __float_as_int(efeat[e]));
    }
}

// ---------------------------------------------------------------------------
// Dual GEMM with packed fp32x2 FMAs:
//   h   = feat @ Wp^T + bp  (fp16 -> g_hh)
//   out = feat @ Ws^T + bs  (fp32 -> d_out)
// ---------------------------------------------------------------------------
__global__ __launch_bounds__(256, 2) void gemm_dual(const float* __restrict__ feat,
                                                    const float* __restrict__ bp,
                                                    const float* __restrict__ bs,
                                                    float* __restrict__ out) {
    __shared__ float2 As2[TM][TK + 2];   // duplicated pairs
    __shared__ float Wps[TK][F];
    __shared__ float Wss[TK][F];

    int tid  = threadIdx.x;
    int row0 = blockIdx.x * TM;
    int tr   = tid >> 4;
    int tc   = tid & 15;

    u64 accP[4][4];
    u64 accS[4][4];
    const u64 z = pack2(0.f, 0.f);
#pragma unroll
    for (int r = 0; r < 4; r++)
#pragma unroll
        for (int c = 0; c < 4; c++) { accP[r][c] = z; accS[r][c] = z; }

    for (int kt = 0; kt < F; kt += TK) {
#pragma unroll
        for (int j = 0; j < 2; j++) {
            int f4 = tid + j * 256;
            int r  = f4 >> 3;
            int k4 = f4 & 7;
            int gr = row0 + r;
            float4 v = make_float4(0.f, 0.f, 0.f, 0.f);
            if (gr < N_NODES)
                v = *(const float4*)&feat[gr * F + kt + k4 * 4];
            As2[r][k4 * 4 + 0] = make_float2(v.x, v.x);
            As2[r][k4 * 4 + 1] = make_float2(v.y, v.y);
            As2[r][k4 * 4 + 2] = make_float2(v.z, v.z);
            As2[r][k4 * 4 + 3] = make_float2(v.w, v.w);
        }
#pragma unroll
        for (int j = 0; j < 4; j++) {
            int f4 = tid + j * 256;
            int k  = f4 >> 5;
            int c4 = f4 & 31;
            *(float4*)&Wps[k][c4 * 4] = *(const float4*)&g_WpT[(kt + k) * F + c4 * 4];
            *(float4*)&Wss[k][c4 * 4] = *(const float4*)&g_WsT[(kt + k) * F + c4 * 4];
        }
        __syncthreads();

#pragma unroll
        for (int kk = 0; kk < TK; kk++) {
            u64 a[4];
#pragma unroll
            for (int r = 0; r < 4; r++)
                a[r] = *(const u64*)&As2[tr * 4 + r][kk];   // LDS.64 pre-packed
            ulonglong2 p0 = *(const ulonglong2*)&Wps[kk][tc * 4];
            ulonglong2 p1 = *(const ulonglong2*)&Wps[kk][64 + tc * 4];
            ulonglong2 s0 = *(const ulonglong2*)&Wss[kk][tc * 4];
            ulonglong2 s1 = *(const ulonglong2*)&Wss[kk][64 + tc * 4];
#pragma unroll
            for (int r = 0; r < 4; r++) {
                accP[r][0] = fma2(a[r], p0.x, accP[r][0]);
                accP[r][1] = fma2(a[r], p0.y, accP[r][1]);
                accP[r][2] = fma2(a[r], p1.x, accP[r][2]);
                accP[r][3] = fma2(a[r], p1.y, accP[r][3]);
                accS[r][0] = fma2(a[r], s0.x, accS[r][0]);
                accS[r][1] = fma2(a[r], s0.y, accS[r][1]);
                accS[r][2] = fma2(a[r], s1.x, accS[r][2]);
                accS[r][3] = fma2(a[r], s1.y, accS[r][3]);
            }
        }
        __syncthreads();
    }

    int c0 = tc * 4;
    int c1 = 64 + tc * 4;
    float4 bpv0 = *(const float4*)&bp[c0];
    float4 bpv1 = *(const float4*)&bp[c1];
    float4 bsv0 = *(const float4*)&bs[c0];
    float4 bsv1 = *(const float4*)&bs[c1];
#pragma unroll
    for (int r = 0; r < 4; r++) {
        int gr = row0 + tr * 4 + r;
        if (gr < N_NODES) {
            float4 hp0, hp1, os0, os1;
            unpack2(accP[r][0], hp0.x, hp0.y);
            unpack2(accP[r][1], hp0.z, hp0.w);
            unpack2(accP[r][2], hp1.x, hp1.y);
            unpack2(accP[r][3], hp1.z, hp1.w);
            unpack2(accS[r][0], os0.x, os0.y);
            unpack2(accS[r][1], os0.z, os0.w);
            unpack2(accS[r][2], os1.x, os1.y);
            unpack2(accS[r][3], os1.z, os1.w);
            hp0.x += bpv0.x; hp0.y += bpv0.y; hp0.z += bpv0.z; hp0.w += bpv0.w;
            hp1.x += bpv1.x; hp1.y += bpv1.y; hp1.z += bpv1.z; hp1.w += bpv1.w;
            os0.x += bsv0.x; os0.y += bsv0.y; os0.z += bsv0.z; os0.w += bsv0.w;
            os1.x += bsv1.x; os1.y += bsv1.y; os1.z += bsv1.z; os1.w += bsv1.w;

            // h -> fp16 pairs (8B per 4 features)
            __half2 ha = __float22half2_rn(make_float2(hp0.x, hp0.y));
            __half2 hb = __float22half2_rn(make_float2(hp0.z, hp0.w));
            __half2 hc = __float22half2_rn(make_float2(hp1.x, hp1.y));
            __half2 hd = __float22half2_rn(make_float2(hp1.z, hp1.w));
            uint2 u0, u1;
            u0.x = *(unsigned int*)&ha;  u0.y = *(unsigned int*)&hb;
            u1.x = *(unsigned int*)&hc;  u1.y = *(unsigned int*)&hd;
            *(uint2*)&g_hh[gr * (F / 2) + tc * 2]      = u0;
            *(uint2*)&g_hh[gr * (F / 2) + 32 + tc * 2] = u1;

            *(float4*)&out[gr * F + c0] = os0;
            *(float4*)&out[gr * F + c1] = os1;
        }
    }
}

// ---------------------------------------------------------------------------
// Aggregation: warp per destination node, gather-only.
// Chunked lane-parallel records: ONE coalesced LDG fetches 32 edge records;
// each lane computes its own m = exp(-w/wsum) (one exp per 32 edges);
// inner loop = 2 SHFL + 1 independent LDG.64 + FMAs, unrolled 4 so the
// gathers issue back-to-back (short dependent chain, high MLP).
// ---------------------------------------------------------------------------
__global__ __launch_bounds__(256) void agg_kernel(float* __restrict__ out) {
    int node = (blockIdx.x * blockDim.x + threadIdx.x) >> 5;
    int lane = threadIdx.x & 31;
    if (node >= N_NODES) return;

    int e0 = g_off[node];
    int e1 = g_off[node + 1];
    int deg = e1 - e0;
    if (deg == 0) return;   // agg contributes 0 (matches max(deg,1) semantics)

    const unsigned FULL = 0xffffffffu;

    // wsum: one strided coalesced pass + warp reduce
    float ws = 0.f;
    for (int e = e0 + lane; e < e1; e += 32)
        ws += __int_as_float(__ldg(&g_edges[e].y));
#pragma unroll
    for (int o = 16; o > 0; o >>= 1)
        ws += __shfl_xor_sync(FULL, ws, o);

    float inv_ws  = __fdividef(1.0f, ws);
    float inv_deg = __fdividef(1.0f, (float)deg);

    float4 acc = make_float4(0.f, 0.f, 0.f, 0.f);
    const int hb = lane * 2;

    for (int base = e0; base < e1; base += 32) {
        int cnt = min(32, e1 - base);
        // lane-parallel: lane i owns record i of this chunk (coalesced LDG)
        int  s_own = 0;
        float m_own = 0.f;
        if (lane < cnt) {
            int2 rec = __ldg(&g_edges[base + lane]);
            s_own = rec.x;
            m_own = __expf(-__int_as_float(rec.y) * inv_ws);
        }
#pragma unroll 4
        for (int i = 0; i < cnt; i++) {
            int   s = __shfl_sync(FULL, s_own, i);
            float m = __shfl_sync(FULL, m_own, i);
            uint2 q = *(const uint2*)&g_hh[s * (F / 2) + hb];
            float2 a = __half22float2(*(__half2*)&q.x);
            float2 b = __half22float2(*(__half2*)&q.y);
            acc.x = fmaf(m, a.x, acc.x);
            acc.y = fmaf(m, a.y, acc.y);
            acc.z = fmaf(m, b.x, acc.z);
            acc.w = fmaf(m, b.y, acc.w);
        }
    }

    float4 o = *(const float4*)&out[node * F + lane * 4];
    o.x += acc.x * inv_deg;
    o.y += acc.y * inv_deg;
    o.z += acc.z * inv_deg;
    o.w += acc.w * inv_deg;
    *(float4*)&out[node * F + lane * 4] = o;
}

// ---------------------------------------------------------------------------
extern "C" void kernel_launch(void* const* d_in, const int* in_sizes, int n_in,
                              void* d_out, int out_size) {
    const float* feat  = (const float*)d_in[0];
    const float* efeat = (const float*)d_in[1];
    const int*   src   = (const int*)d_in[2];
    const int*   dst   = (const int*)d_in[3];
    const float* Wp    = (const float*)d_in[4];
    const float* bp    = (const float*)d_in[5];
    const float* Ws    = (const float*)d_in[6];
    const float* bs    = (const float*)d_in[7];
    float* out = (float*)d_out;

    zero_transpose_kernel<<<(N_NODES + 255) / 256, 256>>>(Wp, Ws);
    hist_kernel<<<(N_EDGES + 255) / 256, 256>>>(dst);
    scan_kernel<<<1, 1024>>>();
    scatter_kernel<<<(N_EDGES + 255) / 256, 256>>>(efeat, src, dst);
    gemm_dual<<<(N_NODES + TM - 1) / TM, 256>>>(feat, bp, bs, out);
    agg_kernel<<<(N_NODES * 32 + 255) / 256, 256>>>(out);
}

// round 15
// speedup vs baseline: 1.4883x; 1.4883x over previous
#include <cuda_runtime.h>
#include <cuda_fp16.h>
#include <math.h>

#define N_NODES 50000
#define N_EDGES 800000
#define F 128
#define TM 64
#define TK 32
#define NB ((N_NODES + 255) / 256)   // 196 scan blocks

typedef unsigned long long u64;

// Scratch (allocation-free rule: __device__ globals)
__device__ __half2 g_hh[N_NODES * (F / 2)];  // h = feat@Wp^T+bp, fp16 pairs
__device__ float g_WpT[F * F];          // W_pool transposed: [k][c]
__device__ float g_WsT[F * F];          // W_self transposed: [k][c]
__device__ int   g_count[N_NODES];      // in-degree histogram
__device__ int   g_off[N_NODES + 1];    // CSR row offsets (by dst)
__device__ int   g_cursor[N_NODES];     // scatter cursors (init = offsets)
__device__ int2  g_edges[N_EDGES];      // dst-sorted records: {src, bits(w)}
__device__ int   g_blocksum[NB];        // per-block count sums
__device__ int   g_blockoff[NB];        // exclusive prefix of block sums

// ---- packed f32x2 helpers (Blackwell sm_103a; ptxas never auto-fuses) ----
__device__ __forceinline__ u64 pack2(float lo, float hi) {
    u64 r; asm("mov.b64 %0, {%1, %2};" : "=l"(r) : "f"(lo), "f"(hi)); return r;
}
__device__ __forceinline__ u64 fma2(u64 a, u64 b, u64 c) {
    u64 d; asm("fma.rn.f32x2 %0, %1, %2, %3;" : "=l"(d) : "l"(a), "l"(b), "l"(c));
    return d;
}
__device__ __forceinline__ void unpack2(u64 v, float& lo, float& hi) {
    asm("mov.b64 {%0, %1}, %2;" : "=f"(lo), "=f"(hi) : "l"(v));
}

// ---------------------------------------------------------------------------
// Zero histogram + transpose weights (runs every launch; deterministic)
// ---------------------------------------------------------------------------
__global__ void zero_transpose_kernel(const float* __restrict__ Wp,
                                      const float* __restrict__ Ws) {
    int i = blockIdx.x * blockDim.x + threadIdx.x;
    if (i < N_NODES) g_count[i] = 0;
    if (i < F * F) {
        int c = i >> 7;
        int k = i & (F - 1);
        g_WpT[k * F + c] = Wp[c * F + k];
        g_WsT[k * F + c] = Ws[c * F + k];
    }
}

// ---------------------------------------------------------------------------
// In-degree histogram
// ---------------------------------------------------------------------------
__global__ void hist_kernel(const int* __restrict__ dst) {
    int e = blockIdx.x * blockDim.x + threadIdx.x;
    if (e < N_EDGES) atomicAdd(&g_count[dst[e]], 1);
}

// ---------------------------------------------------------------------------
// Parallel scan, phase 1: per-block (256-counter) sums. Coalesced.
// ---------------------------------------------------------------------------
__global__ __launch_bounds__(256) void blocksum_kernel() {
    int tid = threadIdx.x, lane = tid & 31, wid = tid >> 5;
    int idx = blockIdx.x * 256 + tid;
    __shared__ int ws[8];
    int v = (idx < N_NODES) ? g_count[idx] : 0;
#pragma unroll
    for (int o = 16; o > 0; o >>= 1)
        v += __shfl_xor_sync(0xffffffff, v, o);
    if (lane == 0) ws[wid] = v;
    __syncthreads();
    if (tid == 0) {
        int s = 0;
#pragma unroll
        for (int i = 0; i < 8; i++) s += ws[i];
        g_blocksum[blockIdx.x] = s;
    }
}

// ---------------------------------------------------------------------------
// Parallel scan, phase 2: exclusive scan of NB (=196) block sums. 1 block.
// ---------------------------------------------------------------------------
__global__ __launch_bounds__(256) void blockscan_kernel() {
    int tid = threadIdx.x, lane = tid & 31, wid = tid >> 5;
    __shared__ int wsum[8];
    int v = (tid < NB) ? g_blocksum[tid] : 0;
    int incl = v;
#pragma unroll
    for (int o = 1; o < 32; o <<= 1) {
        int t = __shfl_up_sync(0xffffffff, incl, o);
        if (lane >= o) incl += t;
    }
    if (lane == 31) wsum[wid] = incl;
    __syncthreads();
    if (wid == 0) {
        int w = (lane < 8) ? wsum[lane] : 0;
#pragma unroll
        for (int o = 1; o < 8; o <<= 1) {
            int t = __shfl_up_sync(0xffffffff, w, o);
            if (lane >= o) w += t;
        }
        if (lane < 8) wsum[lane] = w;
    }
    __syncthreads();
    int excl = incl - v + (wid > 0 ? wsum[wid - 1] : 0);
    if (tid < NB) g_blockoff[tid] = excl;
}

// ---------------------------------------------------------------------------
// Parallel scan, phase 3: block-local exclusive scan + global offset.
// Writes g_off and g_cursor coalesced.
// ---------------------------------------------------------------------------
__global__ __launch_bounds__(256) void offsets_kernel() {
    int tid = threadIdx.x, lane = tid & 31, wid = tid >> 5;
    int idx = blockIdx.x * 256 + tid;
    __shared__ int wsum[8];
    int v = (idx < N_NODES) ? g_count[idx] : 0;
    int incl = v;
#pragma unroll
    for (int o = 1; o < 32; o <<= 1) {
        int t = __shfl_up_sync(0xffffffff, incl, o);
        if (lane >= o) incl += t;
    }
    if (lane == 31) wsum[wid] = incl;
    __syncthreads();
    if (wid == 0) {
        int w = (lane < 8) ? wsum[lane] : 0;
#pragma unroll
        for (int o = 1; o < 8; o <<= 1) {
            int t = __shfl_up_sync(0xffffffff, w, o);
            if (lane >= o) w += t;
        }
        if (lane < 8) wsum[lane] = w;
    }
    __syncthreads();
    int excl = incl - v + (wid > 0 ? wsum[wid - 1] : 0) + g_blockoff[blockIdx.x];
    if (idx < N_NODES) {
        g_off[idx]    = excl;
        g_cursor[idx] = excl;
    }
    if (idx == N_NODES) g_off[N_NODES] = N_EDGES;
}

// ---------------------------------------------------------------------------
// Scatter packed edge records into dst-sorted order
// ---------------------------------------------------------------------------
__global__ void scatter_kernel(const float* __restrict__ efeat,
                               const int* __restrict__ src,
                               const int* __restrict__ dst) {
    int e = blockIdx.x * blockDim.x + threadIdx.x;
    if (e < N_EDGES) {
        int d = dst[e];
        int pos = atomicAdd(&g_cursor[d], 1);
        g_edges[pos] = make_int2(src[e], __float_as_int(efeat[e]));
    }
}

// ---------------------------------------------------------------------------
// Dual GEMM with packed fp32x2 FMAs:
//   h   = feat @ Wp^T + bp  (fp16 -> g_hh)
//   out = feat @ Ws^T + bs  (fp32 -> d_out)
// ---------------------------------------------------------------------------
__global__ __launch_bounds__(256, 2) void gemm_dual(const float* __restrict__ feat,
                                                    const float* __restrict__ bp,
                                                    const float* __restrict__ bs,
                                                    float* __restrict__ out) {
    __shared__ float2 As2[TM][TK + 2];   // duplicated pairs
    __shared__ float Wps[TK][F];
    __shared__ float Wss[TK][F];

    int tid  = threadIdx.x;
    int row0 = blockIdx.x * TM;
    int tr   = tid >> 4;
    int tc   = tid & 15;

    u64 accP[4][4];
    u64 accS[4][4];
    const u64 z = pack2(0.f, 0.f);
#pragma unroll
    for (int r = 0; r < 4; r++)
#pragma unroll
        for (int c = 0; c < 4; c++) { accP[r][c] = z; accS[r][c] = z; }

    for (int kt = 0; kt < F; kt += TK) {
#pragma unroll
        for (int j = 0; j < 2; j++) {
            int f4 = tid + j * 256;
            int r  = f4 >> 3;
            int k4 = f4 & 7;
            int gr = row0 + r;
            float4 v = make_float4(0.f, 0.f, 0.f, 0.f);
            if (gr < N_NODES)
                v = *(const float4*)&feat[gr * F + kt + k4 * 4];
            As2[r][k4 * 4 + 0] = make_float2(v.x, v.x);
            As2[r][k4 * 4 + 1] = make_float2(v.y, v.y);
            As2[r][k4 * 4 + 2] = make_float2(v.z, v.z);
            As2[r][k4 * 4 + 3] = make_float2(v.w, v.w);
        }
#pragma unroll
        for (int j = 0; j < 4; j++) {
            int f4 = tid + j * 256;
            int k  = f4 >> 5;
            int c4 = f4 & 31;
            *(float4*)&Wps[k][c4 * 4] = *(const float4*)&g_WpT[(kt + k) * F + c4 * 4];
            *(float4*)&Wss[k][c4 * 4] = *(const float4*)&g_WsT[(kt + k) * F + c4 * 4];
        }
        __syncthreads();

#pragma unroll
        for (int kk = 0; kk < TK; kk++) {
            u64 a[4];
#pragma unroll
            for (int r = 0; r < 4; r++)
                a[r] = *(const u64*)&As2[tr * 4 + r][kk];   // LDS.64 pre-packed
            ulonglong2 p0 = *(const ulonglong2*)&Wps[kk][tc * 4];
            ulonglong2 p1 = *(const ulonglong2*)&Wps[kk][64 + tc * 4];
            ulonglong2 s0 = *(const ulonglong2*)&Wss[kk][tc * 4];
            ulonglong2 s1 = *(const ulonglong2*)&Wss[kk][64 + tc * 4];
#pragma unroll
            for (int r = 0; r < 4; r++) {
                accP[r][0] = fma2(a[r], p0.x, accP[r][0]);
                accP[r][1] = fma2(a[r], p0.y, accP[r][1]);
                accP[r][2] = fma2(a[r], p1.x, accP[r][2]);
                accP[r][3] = fma2(a[r], p1.y, accP[r][3]);
                accS[r][0] = fma2(a[r], s0.x, accS[r][0]);
                accS[r][1] = fma2(a[r], s0.y, accS[r][1]);
                accS[r][2] = fma2(a[r], s1.x, accS[r][2]);
                accS[r][3] = fma2(a[r], s1.y, accS[r][3]);
            }
        }
        __syncthreads();
    }

    int c0 = tc * 4;
    int c1 = 64 + tc * 4;
    float4 bpv0 = *(const float4*)&bp[c0];
    float4 bpv1 = *(const float4*)&bp[c1];
    float4 bsv0 = *(const float4*)&bs[c0];
    float4 bsv1 = *(const float4*)&bs[c1];
#pragma unroll
    for (int r = 0; r < 4; r++) {
        int gr = row0 + tr * 4 + r;
        if (gr < N_NODES) {
            float4 hp0, hp1, os0, os1;
            unpack2(accP[r][0], hp0.x, hp0.y);
            unpack2(accP[r][1], hp0.z, hp0.w);
            unpack2(accP[r][2], hp1.x, hp1.y);
            unpack2(accP[r][3], hp1.z, hp1.w);
            unpack2(accS[r][0], os0.x, os0.y);
            unpack2(accS[r][1], os0.z, os0.w);
            unpack2(accS[r][2], os1.x, os1.y);
            unpack2(accS[r][3], os1.z, os1.w);
            hp0.x += bpv0.x; hp0.y += bpv0.y; hp0.z += bpv0.z; hp0.w += bpv0.w;
            hp1.x += bpv1.x; hp1.y += bpv1.y; hp1.z += bpv1.z; hp1.w += bpv1.w;
            os0.x += bsv0.x; os0.y += bsv0.y; os0.z += bsv0.z; os0.w += bsv0.w;
            os1.x += bsv1.x; os1.y += bsv1.y; os1.z += bsv1.z; os1.w += bsv1.w;

            // h -> fp16 pairs (8B per 4 features)
            __half2 ha = __float22half2_rn(make_float2(hp0.x, hp0.y));
            __half2 hb = __float22half2_rn(make_float2(hp0.z, hp0.w));
            __half2 hc = __float22half2_rn(make_float2(hp1.x, hp1.y));
            __half2 hd = __float22half2_rn(make_float2(hp1.z, hp1.w));
            uint2 u0, u1;
            u0.x = *(unsigned int*)&ha;  u0.y = *(unsigned int*)&hb;
            u1.x = *(unsigned int*)&hc;  u1.y = *(unsigned int*)&hd;
            *(uint2*)&g_hh[gr * (F / 2) + tc * 2]      = u0;
            *(uint2*)&g_hh[gr * (F / 2) + 32 + tc * 2] = u1;

            *(float4*)&out[gr * F + c0] = os0;
            *(float4*)&out[gr * F + c1] = os1;
        }
    }
}

// ---------------------------------------------------------------------------
// Aggregation: warp per destination node, gather-only.
// Lane-parallel records + SHFL broadcast; fp16 gather, fp32 accumulate.
// ---------------------------------------------------------------------------
__global__ __launch_bounds__(256) void agg_kernel(float* __restrict__ out) {
    int node = (blockIdx.x * blockDim.x + threadIdx.x) >> 5;
    int lane = threadIdx.x & 31;
    if (node >= N_NODES) return;

    int e0 = g_off[node];
    int e1 = g_off[node + 1];
    int deg = e1 - e0;
    if (deg == 0) return;   // agg contributes 0 (matches max(deg,1) semantics)

    const unsigned FULL = 0xffffffffu;

    // wsum: one strided coalesced pass + warp reduce
    float ws = 0.f;
    for (int e = e0 + lane; e < e1; e += 32)
        ws += __int_as_float(__ldg(&g_edges[e].y));
#pragma unroll
    for (int o = 16; o > 0; o >>= 1)
        ws += __shfl_xor_sync(FULL, ws, o);

    float inv_ws  = __fdividef(1.0f, ws);
    float inv_deg = __fdividef(1.0f, (float)deg);

    float4 acc = make_float4(0.f, 0.f, 0.f, 0.f);
    const int hb = lane * 2;

    for (int base = e0; base < e1; base += 32) {
        int cnt = min(32, e1 - base);
        int  s_own = 0;
        float m_own = 0.f;
        if (lane < cnt) {
            int2 rec = __ldg(&g_edges[base + lane]);
            s_own = rec.x;
            m_own = __expf(-__int_as_float(rec.y) * inv_ws);
        }
#pragma unroll 4
        for (int i = 0; i < cnt; i++) {
            int   s = __shfl_sync(FULL, s_own, i);
            float m = __shfl_sync(FULL, m_own, i);
            uint2 q = *(const uint2*)&g_hh[s * (F / 2) + hb];
            float2 a = __half22float2(*(__half2*)&q.x);
            float2 b = __half22float2(*(__half2*)&q.y);
            acc.x = fmaf(m, a.x, acc.x);
            acc.y = fmaf(m, a.y, acc.y);
            acc.z = fmaf(m, b.x, acc.z);
            acc.w = fmaf(m, b.y, acc.w);
        }
    }

    float4 o = *(const float4*)&out[node * F + lane * 4];
    o.x += acc.x * inv_deg;
    o.y += acc.y * inv_deg;
    o.z += acc.z * inv_deg;
    o.w += acc.w * inv_deg;
    *(float4*)&out[node * F + lane * 4] = o;
}

// ---------------------------------------------------------------------------
// Launch order puts gemm_dual 4th: ncu (-s 5 -c 1) profiles the 4th launch,
// giving gemm visibility next round. Dependencies remain stream-correct:
// gemm needs only zero_transpose; blockscan needs blocksum; offsets needs
// blockscan; scatter needs offsets; agg needs scatter+gemm.
// ---------------------------------------------------------------------------
extern "C" void kernel_launch(void* const* d_in, const int* in_sizes, int n_in,
                              void* d_out, int out_size) {
    const float* feat  = (const float*)d_in[0];
    const float* efeat = (const float*)d_in[1];
    const int*   src   = (const int*)d_in[2];
    const int*   dst   = (const int*)d_in[3];
    const float* Wp    = (const float*)d_in[4];
    const float* bp    = (const float*)d_in[5];
    const float* Ws    = (const float*)d_in[6];
    const float* bs    = (const float*)d_in[7];
    float* out = (float*)d_out;

    zero_transpose_kernel<<<(N_NODES + 255) / 256, 256>>>(Wp, Ws);   // #1
    hist_kernel<<<(N_EDGES + 255) / 256, 256>>>(dst);                // #2
    blocksum_kernel<<<NB, 256>>>();                                  // #3
    gemm_dual<<<(N_NODES + TM - 1) / TM, 256>>>(feat, bp, bs, out);  // #4 (profiled)
    blockscan_kernel<<<1, 256>>>();                                  // #5
    offsets_kernel<<<NB, 256>>>();                                   // #6
    scatter_kernel<<<(N_EDGES + 255) / 256, 256>>>(efeat, src, dst); // #7
    agg_kernel<<<(N_NODES * 32 + 255) / 256, 256>>>(out);            // #8
}